// round 11
// baseline (speedup 1.0000x reference)
#include <cuda_runtime.h>
#include <math.h>

// Fixed shapes: B=32, S=128, V=8, T=66 -> 256 independent sequences.
// One block (64 thr) per sequence, two independent register-resident chains:
//   warp 0: forward  alpha_0 -> alpha_63   warp 1: backward w_127 -> w_64
// u lives in REGISTERS; exchanged per step by __shfl_sync broadcasts.
// No smem / no syncwarp in the scan loop. Meet once: Z = (alpha_63 M) . w_64.
#define TT   66
#define SS   128
#define NSEQ 256
#define NTHR 64

typedef unsigned long long ull;

__device__ float        g_partial[NSEQ];
__device__ unsigned int g_count = 0;

static __device__ __forceinline__ ull pk2(float lo, float hi) {
    ull r; asm("mov.b64 %0, {%1,%2};" : "=l"(r) : "f"(lo), "f"(hi)); return r;
}
static __device__ __forceinline__ void fma2(ull& d, ull a, ull b) {
    asm("fma.rn.f32x2 %0, %1, %2, %0;" : "+l"(d) : "l"(a), "l"(b));
}
static __device__ __forceinline__ void add2(ull& d, ull a, ull b) {
    asm("add.rn.f32x2 %0, %1, %2;" : "=l"(d) : "l"(a), "l"(b));
}
static __device__ __forceinline__ float2 upk2(ull v) {
    float lo, hi; asm("mov.b64 {%0,%1}, %2;" : "=f"(lo), "=f"(hi) : "l"(v));
    return make_float2(lo, hi);
}

__global__ void __launch_bounds__(NTHR) crf_kernel(
    const float* __restrict__ score,       // [B,S,S,T]
    const float* __restrict__ trans,       // [T,T]
    const float* __restrict__ startT,      // [T]
    const float* __restrict__ endT,        // [T]
    const int*   __restrict__ v_label,     // [B*V]
    const int*   __restrict__ role_label,  // [B*V][S]
    float*       __restrict__ out)
{
    __shared__ __align__(16) float esh[2][64*TT];  // [warp][64 rows][66] exp(emis)
    __shared__ __align__(16) float wslab[68];      // warp1 final w_64 (raw)
    __shared__ float sL[2], sScB, sgold[2], swsum, wred[2];
    __shared__ int   sflag;

    const int tid  = threadIdx.x;
    const int lane = tid & 31;
    const int w    = tid >> 5;             // 0 = forward, 1 = backward
    const int seq  = blockIdx.x;
    const int vr   = __ldg(&v_label[seq]);
    const float* erow = score + ((size_t)((seq >> 3)*SS + vr))*SS*TT;

    // ---- gold path: 2 positions per thread ----
    float gold = 0.f;
    #pragma unroll
    for (int p = 0; p < 2; p++) {
        int s  = tid + 64*p;
        int tg = __ldg(&role_label[seq*SS + s]);
        float gg = __ldg(&erow[s*TT + tg]);
        if (s < SS-1) gg += __ldg(&trans[tg*TT + __ldg(&role_label[seq*SS + s + 1])]);
        else          gg += __ldg(&endT[tg]);
        if (s == 0)   gg += __ldg(&startT[tg]);
        gold += gg;
    }
    #pragma unroll
    for (int o = 16; o; o >>= 1) gold += __shfl_xor_sync(~0u, gold, o);
    if (lane == 0) sgold[w] = gold;

    // ---- stage my warp's 64 emission rows, fused with exp ----
    {
        const float4* src = (const float4*)(erow + (w ? 64*TT : 0));
        float4*       dst = (float4*)esh[w];
        #pragma unroll 3
        for (int k = lane; k < (64*TT)/4; k += 32) {
            float4 v = __ldg(&src[k]);
            v.x = __expf(v.x); v.y = __expf(v.y);
            v.z = __expf(v.z); v.w = __expf(v.w);
            dst[k] = v;
        }
    }

    // ---- E registers (dual-interleave) over 33 u-pairs; direction per warp ----
    ull eA[33], eB[33], exA, exB;
    float cx0, cx1, cy0, cy1;
    if (w == 0) {
        // forward: outputs = columns (2l, 2l+1)
        #pragma unroll
        for (int m = 0; m < 33; m++) {
            float2 f0 = __ldg((const float2*)(trans + (2*m  )*TT) + lane);
            float2 f1 = __ldg((const float2*)(trans + (2*m+1)*TT) + lane);
            float a = __expf(f0.x), bq = __expf(f0.y);
            float c = __expf(f1.x), d  = __expf(f1.y);
            eA[m] = pk2(a, d);
            eB[m] = pk2(bq, c);
        }
        // extra outputs 64,65: my own pair's rows
        float2 h0 = __ldg((const float2*)(trans + (2*lane  )*TT + 64));
        float2 h1 = __ldg((const float2*)(trans + (2*lane+1)*TT + 64));
        exA = pk2(__expf(h0.x), __expf(h1.y));
        exB = pk2(__expf(h0.y), __expf(h1.x));
        float2 k0 = __ldg((const float2*)(trans + 64*TT + 64));   // M[64][64..65]
        float2 k1 = __ldg((const float2*)(trans + 65*TT + 64));   // M[65][64..65]
        cx0 = __expf(k0.x); cx1 = __expf(k1.x);   // -> out 64
        cy0 = __expf(k0.y); cy1 = __expf(k1.y);   // -> out 65
    } else {
        // backward: outputs = rows (2l, 2l+1)
        const float* row0 = trans + (2*lane    )*TT;
        const float* row1 = trans + (2*lane + 1)*TT;
        #pragma unroll
        for (int m = 0; m < 33; m++) {
            float2 f0 = __ldg((const float2*)row0 + m);
            float2 f1 = __ldg((const float2*)row1 + m);
            float a = __expf(f0.x), bq = __expf(f0.y);
            float c = __expf(f1.x), d  = __expf(f1.y);
            eA[m] = pk2(a, d);
            eB[m] = pk2(c, bq);
        }
        // extra outputs rows 64,65: sum over my pair's columns
        float2 h0 = __ldg((const float2*)(trans + 64*TT + 2*lane));  // M[64][2l..2l+1]
        float2 h1 = __ldg((const float2*)(trans + 65*TT + 2*lane));  // M[65][2l..2l+1]
        exA = pk2(__expf(h0.x), __expf(h1.y));
        exB = pk2(__expf(h1.x), __expf(h0.y));
        float2 k0 = __ldg((const float2*)(trans + 64*TT + 64));
        float2 k1 = __ldg((const float2*)(trans + 65*TT + 64));
        cx0 = __expf(k0.x); cx1 = __expf(k0.y);   // -> out row 64
        cy0 = __expf(k1.x); cy1 = __expf(k1.y);   // -> out row 65
    }

    float2 bc = w ? __ldg((const float2*)endT + lane) : __ldg((const float2*)startT + lane);
    float2 bx = w ? __ldg((const float2*)(endT + 64)) : __ldg((const float2*)(startT + 64));

    __syncwarp();   // esh half staged (only sync in this warp's life until meet)

    // ---- init state in registers ----
    const float* e0 = esh[w] + (w ? 63*TT : 0);
    float r0   = __expf(bc.x) * e0[2*lane];
    float r1   = __expf(bc.y) * e0[2*lane + 1];
    float x64v = __expf(bx.x) * e0[64];
    float x65v = __expf(bx.y) * e0[65];

    float m0 = fmaxf(fmaxf(r0, r1), fmaxf(x64v, x65v));
    #pragma unroll
    for (int o = 16; o; o >>= 1) m0 = fmaxf(m0, __shfl_xor_sync(~0u, m0, o));
    float sc = __fdividef(1.0f, m0);
    float L  = __logf(m0);

    const int dE = w ? -TT : TT;
    const float* emrow = esh[w] + (w ? 62*TT : TT);

    // ---- one step: pure register exchange (shfl), zero smem/sync ----
    auto STEP = [&](float scale) {
        float2 em  = ((const float2*)emrow)[lane];
        float2 emx = *(const float2*)(emrow + 64);
        ull r01 = pk2(r0, r1);
        ull x01 = pk2(x64v, x65v);
        // extra outputs: own-pair contribution, butterfly, corner terms
        ull XA = 0, XB = 0;
        fma2(XA, r01, exA);
        fma2(XB, r01, exB);
        float2 fa = upk2(XA), fb = upk2(XB);
        float px = fa.x + fb.y;
        float py = fa.y + fb.x;
        #pragma unroll
        for (int o = 1; o < 32; o <<= 1) {
            px += __shfl_xor_sync(~0u, px, o);
            py += __shfl_xor_sync(~0u, py, o);
        }
        px += x64v*cx0 + x65v*cx1;
        py += x64v*cy0 + x65v*cy1;
        // main dot: broadcast each lane's pair
        ull dA0 = 0, dA1 = 0, dB0 = 0, dB1 = 0;
        #pragma unroll
        for (int m = 0; m < 32; m += 2) {
            ull u0 = __shfl_sync(~0u, r01, m);
            ull u1 = __shfl_sync(~0u, r01, m + 1);
            fma2(dA0, u0, eA[m]);     fma2(dB0, u0, eB[m]);
            fma2(dA1, u1, eA[m+1]);   fma2(dB1, u1, eB[m+1]);
        }
        fma2(dA0, x01, eA[32]);
        fma2(dB0, x01, eB[32]);
        add2(dA0, dA0, dA1); add2(dB0, dB0, dB1);
        float2 A = upk2(dA0), Bv = upk2(dB0);
        r0   = (A.x + Bv.y) * (scale * em.x);
        r1   = (A.y + Bv.x) * (scale * em.y);
        x64v = px * (scale * emx.x);
        x65v = py * (scale * emx.y);
        emrow += dE;
    };

    // ---- 63 steps: 7 groups of 8 + tail 7; renorm at group ends ----
    for (int grp = 0; grp < 8; grp++) {
        const int n = (grp == 7) ? 7 : 8;
        #pragma unroll 8
        for (int q = 0; q < n; q++) STEP((q == 0) ? sc : 1.0f);
        float mm = fmaxf(fmaxf(r0, r1), fmaxf(x64v, x65v));
        #pragma unroll
        for (int o = 16; o; o >>= 1) mm = fmaxf(mm, __shfl_xor_sync(~0u, mm, o));
        sc = __fdividef(1.0f, mm);
        L += __logf(mm);
    }
    // invariant: actual = regs * exp(L) * sc   (sc pending)

    // ---- chains meet: warp 1 publishes w_64 (raw) + its scale/L ----
    if (w == 1) {
        ((float2*)wslab)[lane] = make_float2(r0, r1);
        if (lane == 0) {
            *(float2*)(wslab + 64) = make_float2(x64v, x65v);
            sScB = sc; sL[1] = L;
        }
    } else if (lane == 0) {
        sL[0] = L;
    }
    __syncthreads();

    // ---- epilogue (warp 0): Z = sum_j (alpha_63 M)[j] * w_64[j] ----
    if (w == 0) {
        const float scB = sScB;
        ull r01 = pk2(r0, r1);
        ull x01 = pk2(x64v, x65v);
        ull XA = 0, XB = 0;
        fma2(XA, r01, exA);
        fma2(XB, r01, exB);
        float2 fa = upk2(XA), fb = upk2(XB);
        float px = fa.x + fb.y;
        float py = fa.y + fb.x;
        #pragma unroll
        for (int o = 1; o < 32; o <<= 1) {
            px += __shfl_xor_sync(~0u, px, o);
            py += __shfl_xor_sync(~0u, py, o);
        }
        px += x64v*cx0 + x65v*cx1;
        py += x64v*cy0 + x65v*cy1;
        ull dA0 = 0, dA1 = 0, dB0 = 0, dB1 = 0;
        #pragma unroll
        for (int m = 0; m < 32; m += 2) {
            ull u0 = __shfl_sync(~0u, r01, m);
            ull u1 = __shfl_sync(~0u, r01, m + 1);
            fma2(dA0, u0, eA[m]);     fma2(dB0, u0, eB[m]);
            fma2(dA1, u1, eA[m+1]);   fma2(dB1, u1, eB[m+1]);
        }
        fma2(dA0, x01, eA[32]);
        fma2(dB0, x01, eB[32]);
        add2(dA0, dA0, dA1); add2(dB0, dB0, dB1);
        float2 A = upk2(dA0), Bv = upk2(dB0);
        float2 wv = ((const float2*)wslab)[lane];
        float contrib = ((A.x + Bv.y)*sc) * (wv.x*scB)
                      + ((A.y + Bv.x)*sc) * (wv.y*scB);
        if (lane == 0)
            contrib += (px*sc)*(wslab[64]*scB) + (py*sc)*(wslab[65]*scB);
        #pragma unroll
        for (int o = 16; o; o >>= 1) contrib += __shfl_xor_sync(~0u, contrib, o);
        if (lane == 0) swsum = contrib;
    }
    __syncthreads();

    if (tid == 0) {
        float logZ = __logf(swsum) + sL[0] + sL[1];
        __stcg(&g_partial[seq], logZ - (sgold[0] + sgold[1]));
        __threadfence();
        unsigned c0 = atomicAdd(&g_count, 1u);
        sflag = (c0 == NSEQ - 1) ? 1 : 0;
    }
    __syncthreads();

    // ---- fused final reduction in the last block ----
    if (sflag) {
        float v = 0.f;
        #pragma unroll
        for (int p = 0; p < 4; p++) v += __ldcg(&g_partial[tid + 64*p]);
        #pragma unroll
        for (int o = 16; o; o >>= 1) v += __shfl_xor_sync(~0u, v, o);
        if (lane == 0) wred[w] = v;
        __syncthreads();
        if (tid == 0) {
            out[0] = (wred[0] + wred[1]) * (1.0f / (float)NSEQ);
            g_count = 0;                   // reset for next graph replay
        }
    }
}

extern "C" void kernel_launch(void* const* d_in, const int* in_sizes, int n_in,
                              void* d_out, int out_size) {
    const float* score      = (const float*)d_in[0];
    const float* trans      = (const float*)d_in[1];
    const float* startT     = (const float*)d_in[2];
    const float* endT       = (const float*)d_in[3];
    const int*   v_label    = (const int*)d_in[4];
    const int*   role_label = (const int*)d_in[5];
    float* out = (float*)d_out;

    crf_kernel<<<NSEQ, NTHR>>>(score, trans, startT, endT, v_label, role_label, out);
}

// round 12
// speedup vs baseline: 1.8136x; 1.8136x over previous
#include <cuda_runtime.h>
#include <math.h>

// Fixed shapes: B=32, S=128, V=8, T=66 -> 256 independent sequences.
// One block (64 thr) per sequence, TWO independent warp-synchronous chains:
//   warp 0: forward  alpha_0 -> alpha_63   warp 1: backward w_127 -> w_64
// u pairs 0..31 exchanged via smem broadcast LDS; pair 32 (states 64/65) is
// REGISTER-RESIDENT (all lanes hold it). Meet once: Z = (alpha_63 M) . w_64.
#define TT   66
#define SS   128
#define NSEQ 256
#define NTHR 64
#define USTR 72

typedef unsigned long long ull;

__device__ float        g_partial[NSEQ];
__device__ unsigned int g_count = 0;

static __device__ __forceinline__ ull pk2(float lo, float hi) {
    ull r; asm("mov.b64 %0, {%1,%2};" : "=l"(r) : "f"(lo), "f"(hi)); return r;
}
static __device__ __forceinline__ void fma2(ull& d, ull a, ull b) {
    asm("fma.rn.f32x2 %0, %1, %2, %0;" : "+l"(d) : "l"(a), "l"(b));
}
static __device__ __forceinline__ void add2(ull& d, ull a, ull b) {
    asm("add.rn.f32x2 %0, %1, %2;" : "=l"(d) : "l"(a), "l"(b));
}
static __device__ __forceinline__ float2 upk2(ull v) {
    float lo, hi; asm("mov.b64 {%0,%1}, %2;" : "=f"(lo), "=f"(hi) : "l"(v));
    return make_float2(lo, hi);
}

__global__ void __launch_bounds__(NTHR) crf_kernel(
    const float* __restrict__ score,       // [B,S,S,T]
    const float* __restrict__ trans,       // [T,T]
    const float* __restrict__ startT,      // [T]
    const float* __restrict__ endT,        // [T]
    const int*   __restrict__ v_label,     // [B*V]
    const int*   __restrict__ role_label,  // [B*V][S]
    float*       __restrict__ out)
{
    __shared__ __align__(16) float esh[2][64*TT];   // [warp][64 rows][66] exp(emis)
    __shared__ __align__(16) float ubuf[2][2][USTR];// [warp][pingpong] (pairs 0..31)
    __shared__ __align__(16) float wslab[68];       // warp1 final w_64 (raw, incl 64/65)
    __shared__ float sL[2], sScB, sgold[2], swsum, wred[2];
    __shared__ int   sflag;

    const int tid  = threadIdx.x;
    const int lane = tid & 31;
    const int w    = tid >> 5;             // 0 = forward, 1 = backward
    const int seq  = blockIdx.x;
    const int vr   = __ldg(&v_label[seq]);
    const float* erow = score + ((size_t)((seq >> 3)*SS + vr))*SS*TT;

    // ---- gold path: 2 positions per thread ----
    float gold = 0.f;
    #pragma unroll
    for (int p = 0; p < 2; p++) {
        int s  = tid + 64*p;
        int tg = __ldg(&role_label[seq*SS + s]);
        float gg = __ldg(&erow[s*TT + tg]);
        if (s < SS-1) gg += __ldg(&trans[tg*TT + __ldg(&role_label[seq*SS + s + 1])]);
        else          gg += __ldg(&endT[tg]);
        if (s == 0)   gg += __ldg(&startT[tg]);
        gold += gg;
    }
    #pragma unroll
    for (int o = 16; o; o >>= 1) gold += __shfl_xor_sync(~0u, gold, o);
    if (lane == 0) sgold[w] = gold;

    // ---- stage my warp's 64 emission rows, fused with exp ----
    {
        const float4* src = (const float4*)(erow + (w ? 64*TT : 0));
        float4*       dst = (float4*)esh[w];
        #pragma unroll 3
        for (int k = lane; k < (64*TT)/4; k += 32) {
            float4 v = __ldg(&src[k]);
            v.x = __expf(v.x); v.y = __expf(v.y);
            v.z = __expf(v.z); v.w = __expf(v.w);
            dst[k] = v;
        }
    }

    // ---- E registers (dual-interleave); direction per warp ----
    ull eA[33], eB[33], xA[5], xB[5];
    float cx0, cx1, cy0, cy1;
    const int g = lane & 7;
    if (w == 0) {
        #pragma unroll
        for (int m = 0; m < 33; m++) {
            float2 f0 = __ldg((const float2*)(trans + (2*m  )*TT) + lane);
            float2 f1 = __ldg((const float2*)(trans + (2*m+1)*TT) + lane);
            float a = __expf(f0.x), bq = __expf(f0.y);
            float c = __expf(f1.x), d  = __expf(f1.y);
            eA[m] = pk2(a, d);
            eB[m] = pk2(bq, c);
        }
        #pragma unroll
        for (int q = 0; q < 4; q++) {
            int rr = 2*(4*g + q);
            float2 h0 = __ldg((const float2*)(trans + rr*TT + 64));
            float2 h1 = __ldg((const float2*)(trans + (rr+1)*TT + 64));
            xA[q] = pk2(__expf(h0.x), __expf(h1.y));
            xB[q] = pk2(__expf(h0.y), __expf(h1.x));
        }
        xA[4] = 0ULL; xB[4] = 0ULL;   // pair32 handled via corner regs
        float2 k0 = __ldg((const float2*)(trans + 64*TT + 64));
        float2 k1 = __ldg((const float2*)(trans + 65*TT + 64));
        cx0 = __expf(k0.x); cx1 = __expf(k1.x);
        cy0 = __expf(k0.y); cy1 = __expf(k1.y);
    } else {
        const float* row0 = trans + (2*lane    )*TT;
        const float* row1 = trans + (2*lane + 1)*TT;
        #pragma unroll
        for (int m = 0; m < 33; m++) {
            float2 f0 = __ldg((const float2*)row0 + m);
            float2 f1 = __ldg((const float2*)row1 + m);
            float a = __expf(f0.x), bq = __expf(f0.y);
            float c = __expf(f1.x), d  = __expf(f1.y);
            eA[m] = pk2(a, d);
            eB[m] = pk2(c, bq);
        }
        #pragma unroll
        for (int q = 0; q < 4; q++) {
            int rr = 2*(4*g + q);
            float2 h0 = __ldg((const float2*)(trans + 64*TT + rr));
            float2 h1 = __ldg((const float2*)(trans + 65*TT + rr));
            xA[q] = pk2(__expf(h0.x), __expf(h1.y));
            xB[q] = pk2(__expf(h1.x), __expf(h0.y));
        }
        xA[4] = 0ULL; xB[4] = 0ULL;
        float2 k0 = __ldg((const float2*)(trans + 64*TT + 64));
        float2 k1 = __ldg((const float2*)(trans + 65*TT + 64));
        cx0 = __expf(k0.x); cx1 = __expf(k0.y);
        cy0 = __expf(k1.x); cy1 = __expf(k1.y);
    }

    float2 bc = w ? __ldg((const float2*)endT + lane) : __ldg((const float2*)startT + lane);
    float2 bx = w ? __ldg((const float2*)(endT + 64)) : __ldg((const float2*)(startT + 64));

    __syncwarp();

    // ---- init state: pairs in smem, pair 32 in registers (all lanes) ----
    const float* e0 = esh[w] + (w ? 63*TT : 0);
    float r0   = __expf(bc.x) * e0[2*lane];
    float r1   = __expf(bc.y) * e0[2*lane + 1];
    float x64v = __expf(bx.x) * e0[64];
    float x65v = __expf(bx.y) * e0[65];
    float* uc = ubuf[w][0];
    float* un = ubuf[w][1];
    ((float2*)uc)[lane] = make_float2(r0, r1);

    float m0 = fmaxf(fmaxf(r0, r1), fmaxf(x64v, x65v));
    #pragma unroll
    for (int o = 16; o; o >>= 1) m0 = fmaxf(m0, __shfl_xor_sync(~0u, m0, o));
    float sc = __fdividef(1.0f, m0);
    float L  = __logf(m0);
    __syncwarp();

    const int dE = w ? -TT : TT;
    const float* emrow = esh[w] + (w ? 62*TT : TT);

    // ---- one step: extra-state partial+butterfly FIRST (overlaps main fma) ----
    auto STEP = [&](float scale) {
        float2 em  = ((const float2*)emrow)[lane];
        float2 emx = *(const float2*)(emrow + 64);
        ull x01 = pk2(x64v, x65v);               // pair 32 from registers
        // extra states: group-redundant partial over 8 pairs, butterfly early
        const ulonglong2* ux = (const ulonglong2*)(uc + 8*g);
        ulonglong2 va0 = ux[0], va1 = ux[1];
        ull XA = 0, XB = 0;
        fma2(XA, va0.x, xA[0]); fma2(XB, va0.x, xB[0]);
        fma2(XA, va0.y, xA[1]); fma2(XB, va0.y, xB[1]);
        fma2(XA, va1.x, xA[2]); fma2(XB, va1.x, xB[2]);
        fma2(XA, va1.y, xA[3]); fma2(XB, va1.y, xB[3]);
        float2 fa = upk2(XA), fb = upk2(XB);
        float px = fa.x + fb.y;
        float py = fa.y + fb.x;
        px += __shfl_xor_sync(~0u, px, 1);  py += __shfl_xor_sync(~0u, py, 1);
        px += __shfl_xor_sync(~0u, px, 2);  py += __shfl_xor_sync(~0u, py, 2);
        px += __shfl_xor_sync(~0u, px, 4);  py += __shfl_xor_sync(~0u, py, 4);
        px += x64v*cx0 + x65v*cx1;
        py += x64v*cy0 + x65v*cy1;
        // main dot (smem broadcast)
        const ulonglong2* up = (const ulonglong2*)uc;
        ull dA0 = 0, dA1 = 0, dB0 = 0, dB1 = 0;
        #pragma unroll
        for (int i = 0; i < 16; i++) {
            ulonglong2 va = up[i];
            fma2(dA0, va.x, eA[2*i]);   fma2(dB0, va.x, eB[2*i]);
            fma2(dA1, va.y, eA[2*i+1]); fma2(dB1, va.y, eB[2*i+1]);
        }
        fma2(dA0, x01, eA[32]);
        fma2(dB0, x01, eB[32]);
        add2(dA0, dA0, dA1); add2(dB0, dB0, dB1);
        float2 A = upk2(dA0), Bv = upk2(dB0);
        r0   = (A.x + Bv.y) * (scale * em.x);
        r1   = (A.y + Bv.x) * (scale * em.y);
        x64v = px * (scale * emx.x);
        x65v = py * (scale * emx.y);
        ((float2*)un)[lane] = make_float2(r0, r1);
        float* tp = uc; uc = un; un = tp;
        emrow += dE;
        __syncwarp();
    };

    // ---- 63 steps: 7 groups of 8 + tail 7; renorm at group ends ----
    for (int grp = 0; grp < 8; grp++) {
        const int n = (grp == 7) ? 7 : 8;
        #pragma unroll 8
        for (int q = 0; q < n; q++) STEP((q == 0) ? sc : 1.0f);
        float mm = fmaxf(fmaxf(r0, r1), fmaxf(x64v, x65v));
        #pragma unroll
        for (int o = 16; o; o >>= 1) mm = fmaxf(mm, __shfl_xor_sync(~0u, mm, o));
        sc = __fdividef(1.0f, mm);
        L += __logf(mm);
    }
    // invariant: actual = stored * exp(L) * sc   (sc pending)

    // ---- chains meet ----
    if (w == 1) {
        ((float2*)wslab)[lane] = make_float2(r0, r1);
        if (lane == 0) {
            *(float2*)(wslab + 64) = make_float2(x64v, x65v);
            sScB = sc; sL[1] = L;
        }
    } else if (lane == 0) {
        sL[0] = L;
    }
    __syncthreads();

    // ---- epilogue (warp 0): Z = sum_j (alpha_63 M)[j] * w_64[j] ----
    if (w == 0) {
        const float scB = sScB;
        ull x01 = pk2(x64v, x65v);
        const ulonglong2* ux = (const ulonglong2*)(uc + 8*g);
        ulonglong2 va0 = ux[0], va1 = ux[1];
        ull XA = 0, XB = 0;
        fma2(XA, va0.x, xA[0]); fma2(XB, va0.x, xB[0]);
        fma2(XA, va0.y, xA[1]); fma2(XB, va0.y, xB[1]);
        fma2(XA, va1.x, xA[2]); fma2(XB, va1.x, xB[2]);
        fma2(XA, va1.y, xA[3]); fma2(XB, va1.y, xB[3]);
        float2 fa = upk2(XA), fb = upk2(XB);
        float px = fa.x + fb.y;
        float py = fa.y + fb.x;
        px += __shfl_xor_sync(~0u, px, 1);  py += __shfl_xor_sync(~0u, py, 1);
        px += __shfl_xor_sync(~0u, px, 2);  py += __shfl_xor_sync(~0u, py, 2);
        px += __shfl_xor_sync(~0u, px, 4);  py += __shfl_xor_sync(~0u, py, 4);
        px += x64v*cx0 + x65v*cx1;
        py += x64v*cy0 + x65v*cy1;
        const ulonglong2* up = (const ulonglong2*)uc;
        ull dA0 = 0, dA1 = 0, dB0 = 0, dB1 = 0;
        #pragma unroll
        for (int i = 0; i < 16; i++) {
            ulonglong2 va = up[i];
            fma2(dA0, va.x, eA[2*i]);   fma2(dB0, va.x, eB[2*i]);
            fma2(dA1, va.y, eA[2*i+1]); fma2(dB1, va.y, eB[2*i+1]);
        }
        fma2(dA0, x01, eA[32]);
        fma2(dB0, x01, eB[32]);
        add2(dA0, dA0, dA1); add2(dB0, dB0, dB1);
        float2 A = upk2(dA0), Bv = upk2(dB0);
        float2 wv = ((const float2*)wslab)[lane];
        float contrib = ((A.x + Bv.y)*sc) * (wv.x*scB)
                      + ((A.y + Bv.x)*sc) * (wv.y*scB);
        if (lane == 0)
            contrib += (px*sc)*(wslab[64]*scB) + (py*sc)*(wslab[65]*scB);
        #pragma unroll
        for (int o = 16; o; o >>= 1) contrib += __shfl_xor_sync(~0u, contrib, o);
        if (lane == 0) swsum = contrib;
    }
    __syncthreads();

    if (tid == 0) {
        float logZ = __logf(swsum) + sL[0] + sL[1];
        __stcg(&g_partial[seq], logZ - (sgold[0] + sgold[1]));
        __threadfence();
        unsigned c0 = atomicAdd(&g_count, 1u);
        sflag = (c0 == NSEQ - 1) ? 1 : 0;
    }
    __syncthreads();

    // ---- fused final reduction in the last block ----
    if (sflag) {
        float v = 0.f;
        #pragma unroll
        for (int p = 0; p < 4; p++) v += __ldcg(&g_partial[tid + 64*p]);
        #pragma unroll
        for (int o = 16; o; o >>= 1) v += __shfl_xor_sync(~0u, v, o);
        if (lane == 0) wred[w] = v;
        __syncthreads();
        if (tid == 0) {
            out[0] = (wred[0] + wred[1]) * (1.0f / (float)NSEQ);
            g_count = 0;                   // reset for next graph replay
        }
    }
}

extern "C" void kernel_launch(void* const* d_in, const int* in_sizes, int n_in,
                              void* d_out, int out_size) {
    const float* score      = (const float*)d_in[0];
    const float* trans      = (const float*)d_in[1];
    const float* startT     = (const float*)d_in[2];
    const float* endT       = (const float*)d_in[3];
    const int*   v_label    = (const int*)d_in[4];
    const int*   role_label = (const int*)d_in[5];
    float* out = (float*)d_out;

    crf_kernel<<<NSEQ, NTHR>>>(score, trans, startT, endT, v_label, role_label, out);
}